// round 9
// baseline (speedup 1.0000x reference)
#include <cuda_runtime.h>
#include <cstdint>

// Depthwise 3x3 conv, stride 1, VALID, C=64.
// x: (16, 64, 512, 512) f32, w: (64, 3, 3) f32 -> out: (16, 64, 510, 510) f32
//
// R9: BARRIER-FREE async pipeline. Each thread cp.asyncs its OWN 6 input
// floats per row: 16B (cols x0..x0+3) into region A (tid*16, aligned) and
// 8B (cols x0+4..x0+5) into region B (tid*8, aligned). Every thread then
// reads only smem bytes it wrote itself, so cp.async.wait_group alone
// guarantees visibility -- ZERO __syncthreads in the kernel. All 12 rows'
// copies are issued at block start (one commit-group per row, ~36KB in
// flight per block); the R1 rolling-window FFMA2 loop consumes them behind
// progressive waits.

#define TILE_H 10    // 510 = 51 * 10
#define ROWS_IN (TILE_H + 2)
#define THREADS 128  // 128 threads * 4 cols = 512
#define A_SLOT_B 2048  // bytes per row slot, region A (128 thr * 16B)
#define B_SLOT_B 1024  // bytes per row slot, region B (128 thr * 8B)

typedef unsigned long long u64;

__device__ __forceinline__ u64 fpack2(float lo, float hi) {
    u64 d;
    asm("mov.b64 %0, {%1, %2};" : "=l"(d) : "f"(lo), "f"(hi));
    return d;
}

__device__ __forceinline__ u64 fmul2(u64 a, u64 b) {
    u64 d;
    asm("mul.rn.f32x2 %0, %1, %2;" : "=l"(d) : "l"(a), "l"(b));
    return d;
}

__device__ __forceinline__ u64 ffma2(u64 a, u64 b, u64 c) {
    u64 d;
    asm("fma.rn.f32x2 %0, %1, %2, %3;" : "=l"(d) : "l"(a), "l"(b), "l"(c));
    return d;
}

__device__ __forceinline__ void cp_async16(uint32_t smem_addr,
                                           const float* gptr) {
    asm volatile("cp.async.cg.shared.global [%0], [%1], 16;"
                 :: "r"(smem_addr), "l"(gptr));
}

__device__ __forceinline__ void cp_async8(uint32_t smem_addr,
                                          const float* gptr) {
    asm volatile("cp.async.ca.shared.global [%0], [%1], 8;"
                 :: "r"(smem_addr), "l"(gptr));
}

__device__ __forceinline__ void cp_commit() {
    asm volatile("cp.async.commit_group;");
}

template <int N>
__device__ __forceinline__ void cp_wait() {
    asm volatile("cp.async.wait_group %0;" :: "n"(N));
}

// Progressive wait; r is compile-time in the unrolled loop, branches fold.
__device__ __forceinline__ void cp_wait_rt(int r) {
    if (r == 0) cp_wait<9>();
    else if (r == 1) cp_wait<8>();
    else if (r == 2) cp_wait<7>();
    else if (r == 3) cp_wait<6>();
    else if (r == 4) cp_wait<5>();
    else if (r == 5) cp_wait<4>();
    else if (r == 6) cp_wait<3>();
    else if (r == 7) cp_wait<2>();
    else if (r == 8) cp_wait<1>();
    else cp_wait<0>();
}

__global__ void __launch_bounds__(THREADS)
dwconv3x3_kernel(const float* __restrict__ x,
                 const float* __restrict__ w,
                 float* __restrict__ out) {
    // Region A: ROWS_IN slots of 2048B. Region B: ROWS_IN slots of 1024B.
    __shared__ __align__(16) float smA[ROWS_IN * (A_SLOT_B / 4)];
    __shared__ __align__(16) float smB[ROWS_IN * (B_SLOT_B / 4)];

    const int tile = blockIdx.x;   // 0..50
    const int c    = blockIdx.y;   // 0..63
    const int n    = blockIdx.z;   // 0..15

    const int tid = threadIdx.x;
    const int x0  = tid * 4;               // first owned output column
    const bool last = (x0 == 508);         // thread 127: 2 valid outputs only

    const size_t img_off = ((size_t)(n * 64 + c)) * (512 * 512);
    const size_t out_off = ((size_t)(n * 64 + c)) * (510 * 510);
    const float* img = x + img_off;
    float* o = out + out_off;

    const int r0 = tile * TILE_H;          // first output row of this tile

    // Per-thread smem addresses (each thread touches only its own bytes).
    const uint32_t aBase =
        (uint32_t)__cvta_generic_to_shared(smA) + (uint32_t)(tid * 16);
    const uint32_t bBase =
        (uint32_t)__cvta_generic_to_shared(smB) + (uint32_t)(tid * 8);
    const float* aSrcBase = img + x0;            // + row*512
    // Thread 127's halo (cols 512,513) would run 8B past the allocation on
    // the final image row; its values feed only unstored outputs, so point
    // it somewhere safe.
    const float* bSrcBase = last ? img : img + x0 + 4;

    // Issue the whole tile's copies up front: one commit-group per row.
#pragma unroll
    for (int rr = 0; rr < ROWS_IN; ++rr) {
        const size_t roff = (size_t)(r0 + rr) * 512;
        cp_async16(aBase + rr * A_SLOT_B, aSrcBase + roff);
        cp_async8(bBase + rr * B_SLOT_B, bSrcBase + (last ? 0 : roff));
        cp_commit();
    }

    // Broadcast weights as (w,w) f32x2 pairs.
    const float* wc = w + c * 9;
    u64 wp[9];
#pragma unroll
    for (int i = 0; i < 9; ++i) {
        float wv = __ldg(wc + i);
        wp[i] = fpack2(wv, wv);
    }

    const float* aRd = smA + tid * 4;      // float4 at tid*16 bytes
    const float* bRd = smB + tid * 2;      // float2 at tid*8 bytes

    // Build 5 overlapping pairs for row slot rr (reads own bytes only).
#define MK_PAIRS(DST, RR)                                                      \
    {                                                                          \
        float4 a = *reinterpret_cast<const float4*>(aRd + (RR) * (A_SLOT_B/4));\
        float2 b = *reinterpret_cast<const float2*>(bRd + (RR) * (B_SLOT_B/4));\
        DST[0] = fpack2(a.x, a.y);                                             \
        DST[1] = fpack2(a.y, a.z);                                             \
        DST[2] = fpack2(a.z, a.w);                                             \
        DST[3] = fpack2(a.w, b.x);                                             \
        DST[4] = fpack2(b.x, b.y);                                             \
    }

    // Rolling 3-row window.
    u64 q[3][5];
    cp_wait<ROWS_IN - 2>();   // rows 0,1 landed (groups retire in order)
    MK_PAIRS(q[0], 0)
    MK_PAIRS(q[1], 1)

#pragma unroll
    for (int r = 0; r < TILE_H; ++r) {
        const int top = r % 3;
        const int mid = (r + 1) % 3;
        const int bot = (r + 2) % 3;

        cp_wait_rt(r);        // row r+2 landed; NO __syncthreads needed
        MK_PAIRS(q[bot], r + 2)

        // outputs (x0, x0+1)
        u64 acc01 = fmul2(wp[0], q[top][0]);
        acc01 = ffma2(wp[1], q[top][1], acc01);
        acc01 = ffma2(wp[2], q[top][2], acc01);
        acc01 = ffma2(wp[3], q[mid][0], acc01);
        acc01 = ffma2(wp[4], q[mid][1], acc01);
        acc01 = ffma2(wp[5], q[mid][2], acc01);
        acc01 = ffma2(wp[6], q[bot][0], acc01);
        acc01 = ffma2(wp[7], q[bot][1], acc01);
        acc01 = ffma2(wp[8], q[bot][2], acc01);

        // outputs (x0+2, x0+3)
        u64 acc23 = fmul2(wp[0], q[top][2]);
        acc23 = ffma2(wp[1], q[top][3], acc23);
        acc23 = ffma2(wp[2], q[top][4], acc23);
        acc23 = ffma2(wp[3], q[mid][2], acc23);
        acc23 = ffma2(wp[4], q[mid][3], acc23);
        acc23 = ffma2(wp[5], q[mid][4], acc23);
        acc23 = ffma2(wp[6], q[bot][2], acc23);
        acc23 = ffma2(wp[7], q[bot][3], acc23);
        acc23 = ffma2(wp[8], q[bot][4], acc23);

        // Row stride 510*4 = 2040 B is 8-byte aligned -> STG.64 stores.
        float* orow = o + (size_t)(r0 + r) * 510 + x0;
        *reinterpret_cast<u64*>(orow) = acc01;
        if (!last) {
            *reinterpret_cast<u64*>(orow + 2) = acc23;
        }
    }
#undef MK_PAIRS
}

extern "C" void kernel_launch(void* const* d_in, const int* in_sizes, int n_in,
                              void* d_out, int out_size) {
    const float* x = (const float*)d_in[0];
    const float* w = (const float*)d_in[1];
    // Defensive: metadata order is (x, weight); swap if sizes say otherwise.
    if (n_in >= 2 && in_sizes[0] < in_sizes[1]) {
        const float* t = x; x = w; w = t;
    }
    float* out = (float*)d_out;

    dim3 grid(51, 64, 16); // 510/TILE_H row tiles, C, N
    dwconv3x3_kernel<<<grid, THREADS>>>(x, w, out);
}

// round 10
// speedup vs baseline: 1.1540x; 1.1540x over previous
#include <cuda_runtime.h>
#include <cstdint>

// Depthwise 3x3 conv, stride 1, VALID, C=64.
// x: (16, 64, 512, 512) f32, w: (64, 3, 3) f32 -> out: (16, 64, 510, 510) f32
//
// R10 = R8 (best: 305us, DRAM=87.3%) with coarser pipeline granularity:
// the 12-row tile prefetch is committed as 6 groups of 2 rows, and the
// consume loop waits+syncs only when the wait level changes -> 6 barriers
// per block instead of 12. Layout, rolling-window FFMA2 loop, and stores
// are identical to R8.

#define TILE_H 10    // 510 = 51 * 10
#define ROWS_IN (TILE_H + 2)
#define THREADS 128  // 128 threads * 4 cols = 512
#define SLOT_F 520   // floats per smem row slot (512 data + 2 zero + pad)

typedef unsigned long long u64;

__device__ __forceinline__ u64 fpack2(float lo, float hi) {
    u64 d;
    asm("mov.b64 %0, {%1, %2};" : "=l"(d) : "f"(lo), "f"(hi));
    return d;
}

__device__ __forceinline__ u64 fmul2(u64 a, u64 b) {
    u64 d;
    asm("mul.rn.f32x2 %0, %1, %2;" : "=l"(d) : "l"(a), "l"(b));
    return d;
}

__device__ __forceinline__ u64 ffma2(u64 a, u64 b, u64 c) {
    u64 d;
    asm("fma.rn.f32x2 %0, %1, %2, %3;" : "=l"(d) : "l"(a), "l"(b), "l"(c));
    return d;
}

__device__ __forceinline__ void cp_async16(uint32_t smem_addr,
                                           const float* gptr) {
    asm volatile("cp.async.cg.shared.global [%0], [%1], 16;"
                 :: "r"(smem_addr), "l"(gptr));
}

__device__ __forceinline__ void cp_commit() {
    asm volatile("cp.async.commit_group;");
}

template <int N>
__device__ __forceinline__ void cp_wait() {
    asm volatile("cp.async.wait_group %0;" :: "n"(N));
}

// Build 5 overlapping f32x2 pairs from a smem row slot (uniform; cols
// 512/513 hold zeros so thread 127 needs no branch).
__device__ __forceinline__ void pairs_from_smem(const float* srow, int x0,
                                                u64 q[5]) {
    float4 a = *reinterpret_cast<const float4*>(srow + x0);
    float2 b = *reinterpret_cast<const float2*>(srow + x0 + 4);
    q[0] = fpack2(a.x, a.y);
    q[1] = fpack2(a.y, a.z);
    q[2] = fpack2(a.z, a.w);
    q[3] = fpack2(a.w, b.x);
    q[4] = fpack2(b.x, b.y);
}

__global__ void __launch_bounds__(THREADS)
dwconv3x3_kernel(const float* __restrict__ x,
                 const float* __restrict__ w,
                 float* __restrict__ out) {
    __shared__ __align__(16) float sm[ROWS_IN * SLOT_F];

    const int tile = blockIdx.x;   // 0..50
    const int c    = blockIdx.y;   // 0..63
    const int n    = blockIdx.z;   // 0..15

    const int tid = threadIdx.x;
    const int x0  = tid * 4;               // first owned output column
    const bool last = (x0 == 508);         // thread 127: 2 valid outputs only

    const size_t img_off = ((size_t)(n * 64 + c)) * (512 * 512);
    const size_t out_off = ((size_t)(n * 64 + c)) * (510 * 510);
    const float* img = x + img_off;
    float* o = out + out_off;

    const int r0 = tile * TILE_H;          // first output row of this tile

    // Issue the whole tile's loads up front: one 16B cp.async per thread per
    // row, committed as 6 groups of 2 rows. ~25KB in flight per block.
    const uint32_t smem_base =
        (uint32_t)__cvta_generic_to_shared(sm) + (uint32_t)(x0 * 4);
#pragma unroll
    for (int g = 0; g < ROWS_IN / 2; ++g) {
        const int rr = g * 2;
        cp_async16(smem_base + rr * (SLOT_F * 4),
                   img + (size_t)(r0 + rr) * 512 + x0);
        cp_async16(smem_base + (rr + 1) * (SLOT_F * 4),
                   img + (size_t)(r0 + rr + 1) * 512 + x0);
        cp_commit();
    }

    // Zero the 2 halo floats of each slot (cols 512/513). Disjoint from the
    // cp.async target range, so no race.
    if (tid < ROWS_IN) {
        *reinterpret_cast<float2*>(sm + tid * SLOT_F + 512) =
            make_float2(0.0f, 0.0f);
    }

    // Broadcast weights as (w,w) f32x2 pairs.
    const float* wc = w + c * 9;
    u64 wp[9];
#pragma unroll
    for (int i = 0; i < 9; ++i) {
        float wv = __ldg(wc + i);
        wp[i] = fpack2(wv, wv);
    }

    // Rolling 3-row window of overlapping pairs.
    u64 q[3][5];
    cp_wait<5>();             // group 0 (rows 0,1) retired
    __syncthreads();
    pairs_from_smem(sm + 0 * SLOT_F, x0, q[0]);
    pairs_from_smem(sm + 1 * SLOT_F, x0, q[1]);

#pragma unroll
    for (int r = 0; r < TILE_H; ++r) {
        const int top = r % 3;
        const int mid = (r + 1) % 3;
        const int bot = (r + 2) % 3;

        // Row r+2 lives in group (r+2)/2; wait+sync only on even r (when a
        // new group is first needed). r is compile-time; branches fold.
        if (r == 0)      { cp_wait<4>(); __syncthreads(); }
        else if (r == 2) { cp_wait<3>(); __syncthreads(); }
        else if (r == 4) { cp_wait<2>(); __syncthreads(); }
        else if (r == 6) { cp_wait<1>(); __syncthreads(); }
        else if (r == 8) { cp_wait<0>(); __syncthreads(); }

        pairs_from_smem(sm + (r + 2) * SLOT_F, x0, q[bot]);

        // outputs (x0, x0+1)
        u64 acc01 = fmul2(wp[0], q[top][0]);
        acc01 = ffma2(wp[1], q[top][1], acc01);
        acc01 = ffma2(wp[2], q[top][2], acc01);
        acc01 = ffma2(wp[3], q[mid][0], acc01);
        acc01 = ffma2(wp[4], q[mid][1], acc01);
        acc01 = ffma2(wp[5], q[mid][2], acc01);
        acc01 = ffma2(wp[6], q[bot][0], acc01);
        acc01 = ffma2(wp[7], q[bot][1], acc01);
        acc01 = ffma2(wp[8], q[bot][2], acc01);

        // outputs (x0+2, x0+3)
        u64 acc23 = fmul2(wp[0], q[top][2]);
        acc23 = ffma2(wp[1], q[top][3], acc23);
        acc23 = ffma2(wp[2], q[top][4], acc23);
        acc23 = ffma2(wp[3], q[mid][2], acc23);
        acc23 = ffma2(wp[4], q[mid][3], acc23);
        acc23 = ffma2(wp[5], q[mid][4], acc23);
        acc23 = ffma2(wp[6], q[bot][2], acc23);
        acc23 = ffma2(wp[7], q[bot][3], acc23);
        acc23 = ffma2(wp[8], q[bot][4], acc23);

        // Row stride 510*4 = 2040 B is 8-byte aligned -> STG.64 stores.
        float* orow = o + (size_t)(r0 + r) * 510 + x0;
        *reinterpret_cast<u64*>(orow) = acc01;
        if (!last) {
            *reinterpret_cast<u64*>(orow + 2) = acc23;
        }
    }
}

extern "C" void kernel_launch(void* const* d_in, const int* in_sizes, int n_in,
                              void* d_out, int out_size) {
    const float* x = (const float*)d_in[0];
    const float* w = (const float*)d_in[1];
    // Defensive: metadata order is (x, weight); swap if sizes say otherwise.
    if (n_in >= 2 && in_sizes[0] < in_sizes[1]) {
        const float* t = x; x = w; w = t;
    }
    float* out = (float*)d_out;

    dim3 grid(51, 64, 16); // 510/TILE_H row tiles, C, N
    dwconv3x3_kernel<<<grid, THREADS>>>(x, w, out);
}

// round 11
// speedup vs baseline: 1.2608x; 1.0925x over previous
#include <cuda_runtime.h>
#include <cstdint>

// Depthwise 3x3 conv, stride 1, VALID, C=64.
// x: (16, 64, 512, 512) f32, w: (64, 3, 3) f32 -> out: (16, 64, 510, 510) f32
//
// R11 = R8 pipeline (per-row cp.async commit groups, progressive
// wait_group + __syncthreads each row -- proven best at 305us/87.3% DRAM)
// with a smaller tile to raise concurrent blocks per SM:
//   TILE_H 10 -> 6 (ROWS_IN = 8), SLOT_F 520 -> 516 (16B-aligned slots),
//   __launch_bounds__(128, 12).
// Smem 16.5KB + regs<=42 -> 12 blocks/SM (was 9). More independent
// per-block prefetch pipelines in flight -> higher sustained DRAM. Halo
// overhead 8/6 rows is L2-absorbed (measured in R1/R7).

#define TILE_H 6     // 510 = 85 * 6
#define ROWS_IN (TILE_H + 2)
#define THREADS 128  // 128 threads * 4 cols = 512
#define SLOT_F 516   // floats per smem row slot (512 data + 2 zero + 2 pad)

typedef unsigned long long u64;

__device__ __forceinline__ u64 fpack2(float lo, float hi) {
    u64 d;
    asm("mov.b64 %0, {%1, %2};" : "=l"(d) : "f"(lo), "f"(hi));
    return d;
}

__device__ __forceinline__ u64 fmul2(u64 a, u64 b) {
    u64 d;
    asm("mul.rn.f32x2 %0, %1, %2;" : "=l"(d) : "l"(a), "l"(b));
    return d;
}

__device__ __forceinline__ u64 ffma2(u64 a, u64 b, u64 c) {
    u64 d;
    asm("fma.rn.f32x2 %0, %1, %2, %3;" : "=l"(d) : "l"(a), "l"(b), "l"(c));
    return d;
}

__device__ __forceinline__ void cp_async16(uint32_t smem_addr,
                                           const float* gptr) {
    asm volatile("cp.async.cg.shared.global [%0], [%1], 16;"
                 :: "r"(smem_addr), "l"(gptr));
}

__device__ __forceinline__ void cp_commit() {
    asm volatile("cp.async.commit_group;");
}

template <int N>
__device__ __forceinline__ void cp_wait() {
    asm volatile("cp.async.wait_group %0;" :: "n"(N));
}

// Progressive wait; r is compile-time in the unrolled loop, branches fold.
// Row r+2 is group r+2 of ROWS_IN=8; allow ROWS_IN-1-(r+2) younger pending.
__device__ __forceinline__ void cp_wait_rt(int r) {
    if (r == 0) cp_wait<5>();
    else if (r == 1) cp_wait<4>();
    else if (r == 2) cp_wait<3>();
    else if (r == 3) cp_wait<2>();
    else if (r == 4) cp_wait<1>();
    else cp_wait<0>();
}

// Build 5 overlapping f32x2 pairs from a smem row slot (uniform; cols
// 512/513 hold zeros so thread 127 needs no branch).
__device__ __forceinline__ void pairs_from_smem(const float* srow, int x0,
                                                u64 q[5]) {
    float4 a = *reinterpret_cast<const float4*>(srow + x0);
    float2 b = *reinterpret_cast<const float2*>(srow + x0 + 4);
    q[0] = fpack2(a.x, a.y);
    q[1] = fpack2(a.y, a.z);
    q[2] = fpack2(a.z, a.w);
    q[3] = fpack2(a.w, b.x);
    q[4] = fpack2(b.x, b.y);
}

__global__ void __launch_bounds__(THREADS, 12)
dwconv3x3_kernel(const float* __restrict__ x,
                 const float* __restrict__ w,
                 float* __restrict__ out) {
    __shared__ __align__(16) float sm[ROWS_IN * SLOT_F];

    const int tile = blockIdx.x;   // 0..84
    const int c    = blockIdx.y;   // 0..63
    const int n    = blockIdx.z;   // 0..15

    const int tid = threadIdx.x;
    const int x0  = tid * 4;               // first owned output column
    const bool last = (x0 == 508);         // thread 127: 2 valid outputs only

    const size_t img_off = ((size_t)(n * 64 + c)) * (512 * 512);
    const size_t out_off = ((size_t)(n * 64 + c)) * (510 * 510);
    const float* img = x + img_off;
    float* o = out + out_off;

    const int r0 = tile * TILE_H;          // first output row of this tile

    // Issue the whole tile's loads up front: one 16B cp.async per thread per
    // row, one commit-group per row. ~16.5KB in flight per block.
    const uint32_t smem_base =
        (uint32_t)__cvta_generic_to_shared(sm) + (uint32_t)(x0 * 4);
#pragma unroll
    for (int rr = 0; rr < ROWS_IN; ++rr) {
        cp_async16(smem_base + rr * (SLOT_F * 4),
                   img + (size_t)(r0 + rr) * 512 + x0);
        cp_commit();
    }

    // Zero the 2 halo floats of each slot (cols 512/513). Disjoint from the
    // cp.async target range, so no race.
    if (tid < ROWS_IN) {
        *reinterpret_cast<float2*>(sm + tid * SLOT_F + 512) =
            make_float2(0.0f, 0.0f);
    }

    // Broadcast weights as (w,w) f32x2 pairs.
    const float* wc = w + c * 9;
    u64 wp[9];
#pragma unroll
    for (int i = 0; i < 9; ++i) {
        float wv = __ldg(wc + i);
        wp[i] = fpack2(wv, wv);
    }

    // Rolling 3-row window of overlapping pairs.
    u64 q[3][5];
    cp_wait<ROWS_IN - 2>();   // rows 0,1 landed (groups retire in order)
    __syncthreads();
    pairs_from_smem(sm + 0 * SLOT_F, x0, q[0]);
    pairs_from_smem(sm + 1 * SLOT_F, x0, q[1]);

#pragma unroll
    for (int r = 0; r < TILE_H; ++r) {
        const int top = r % 3;
        const int mid = (r + 1) % 3;
        const int bot = (r + 2) % 3;

        cp_wait_rt(r);        // row r+2 landed
        __syncthreads();

        pairs_from_smem(sm + (r + 2) * SLOT_F, x0, q[bot]);

        // outputs (x0, x0+1)
        u64 acc01 = fmul2(wp[0], q[top][0]);
        acc01 = ffma2(wp[1], q[top][1], acc01);
        acc01 = ffma2(wp[2], q[top][2], acc01);
        acc01 = ffma2(wp[3], q[mid][0], acc01);
        acc01 = ffma2(wp[4], q[mid][1], acc01);
        acc01 = ffma2(wp[5], q[mid][2], acc01);
        acc01 = ffma2(wp[6], q[bot][0], acc01);
        acc01 = ffma2(wp[7], q[bot][1], acc01);
        acc01 = ffma2(wp[8], q[bot][2], acc01);

        // outputs (x0+2, x0+3)
        u64 acc23 = fmul2(wp[0], q[top][2]);
        acc23 = ffma2(wp[1], q[top][3], acc23);
        acc23 = ffma2(wp[2], q[top][4], acc23);
        acc23 = ffma2(wp[3], q[mid][2], acc23);
        acc23 = ffma2(wp[4], q[mid][3], acc23);
        acc23 = ffma2(wp[5], q[mid][4], acc23);
        acc23 = ffma2(wp[6], q[bot][2], acc23);
        acc23 = ffma2(wp[7], q[bot][3], acc23);
        acc23 = ffma2(wp[8], q[bot][4], acc23);

        // Row stride 510*4 = 2040 B is 8-byte aligned -> STG.64 stores.
        float* orow = o + (size_t)(r0 + r) * 510 + x0;
        *reinterpret_cast<u64*>(orow) = acc01;
        if (!last) {
            *reinterpret_cast<u64*>(orow + 2) = acc23;
        }
    }
}

extern "C" void kernel_launch(void* const* d_in, const int* in_sizes, int n_in,
                              void* d_out, int out_size) {
    const float* x = (const float*)d_in[0];
    const float* w = (const float*)d_in[1];
    // Defensive: metadata order is (x, weight); swap if sizes say otherwise.
    if (n_in >= 2 && in_sizes[0] < in_sizes[1]) {
        const float* t = x; x = w; w = t;
    }
    float* out = (float*)d_out;

    dim3 grid(85, 64, 16); // 510/TILE_H row tiles, C, N
    dwconv3x3_kernel<<<grid, THREADS>>>(x, w, out);
}